// round 6
// baseline (speedup 1.0000x reference)
#include <cuda_runtime.h>
#include <math.h>
#include <stdint.h>

#define NPTS      524288
#define GRIDSZ    512
#define NC        36
#define KIN       129
#define K1PAD     136
#define HID       256
#define NOUT      129
#define NOUT_PAD  160
#define TB        128
#define NTHREADS  1024

#define HS_STRIDE 140          // %32=12 -> conflict-free A frags
#define H1_STRIDE 260          // %32=4
#define WS_STRIDE 264          // W1 slabs: %32=8 -> conflict-free B frags
#define WS2_STRIDE 168         // W2 slabs: %32=8
#define WS_BUF    (32*WS_STRIDE)              // 8448 floats per 32-row W1 slab
#define WS2_BUF   (32*WS2_STRIDE)             // 5376 floats per 32-row W2 slab
#define SM_A_FLOATS (TB*H1_STRIDE)            // 33280 (union: hs then h1s)
#define SM_WS_OFF   SM_A_FLOATS
#define SM_B1_OFF   (SM_WS_OFF + 2*WS_BUF)    // 50176
#define SM_B2_OFF   (SM_B1_OFF + HID)         // 50432
#define SM_FLOATS   (SM_B2_OFF + NOUT_PAD)    // 50592
#define SMEM_BYTES  (SM_FLOATS*4)             // 202368 B

// device-global scratch (sanctioned mechanism)
__device__ float g_planesT[3*GRIDSZ*GRIDSZ*NC];   // [i][y][x][c]
__device__ float g_linesT[3*GRIDSZ*NC];           // [i][l][c]
__device__ float g_W1p[K1PAD*HID];                // tf32-rounded, zero-padded rows
__device__ float g_W2p[HID*NOUT_PAD];             // tf32-rounded, zero-padded cols

__device__ __forceinline__ unsigned f2tf(float x) {
    unsigned r; asm("cvt.rna.tf32.f32 %0, %1;" : "=r"(r) : "f"(x)); return r;
}
__device__ __forceinline__ float f2tff(float x) { return __uint_as_float(f2tf(x)); }

// ---------------- coalesced plane transpose ----------------
__global__ void __launch_bounds__(256) transpose_planes(const float* __restrict__ planes) {
    __shared__ float tile[8][32*37];
    int wid = threadIdx.x >> 5, lane = threadIdx.x & 31;
    int gw = blockIdx.x * 8 + wid;
    int cell0 = gw * 32;
    int i = cell0 / (GRIDSZ*GRIDSZ);
    int rem = cell0 - i*GRIDSZ*GRIDSZ;
    int y = rem >> 9;
    int x0 = rem & (GRIDSZ-1);
    const float* src = planes + (long)i*NC*GRIDSZ*GRIDSZ + (long)y*GRIDSZ + x0 + lane;
    float* t = tile[wid];
    #pragma unroll
    for (int c = 0; c < NC; c++)
        t[lane*37 + c] = src[(long)c*GRIDSZ*GRIDSZ];
    __syncwarp();
    float* dst = g_planesT + (long)cell0 * NC;
    #pragma unroll
    for (int k = 0; k < 9; k++) {
        int flat = k*32 + lane;
        int fo = flat * 4;
        int cc = fo / NC, c = fo - cc*NC;
        float4 v = make_float4(t[cc*37+c], t[cc*37+c+1], t[cc*37+c+2], t[cc*37+c+3]);
        *(float4*)(dst + fo) = v;
    }
}

__global__ void transpose_lines(const float* __restrict__ lines) {
    int t2 = blockIdx.x * blockDim.x + threadIdx.x;
    if (t2 < 3*GRIDSZ) {
        int j = t2 & (GRIDSZ-1);
        int i = t2 >> 9;
        float* dst = g_linesT + t2*NC;
        const float* src = lines + (long)i*NC*GRIDSZ + j;
        #pragma unroll
        for (int c = 0; c < NC; c++)
            dst[c] = src[(long)c*GRIDSZ];
    }
}

__global__ void pack_weights_kernel(const float* __restrict__ W1,
                                    const float* __restrict__ W2) {
    int idx = blockIdx.x * blockDim.x + threadIdx.x;
    const int T1 = K1PAD*HID;        // 34816
    const int T2 = HID*NOUT_PAD;     // 40960
    if (idx < T1) {
        int k = idx >> 8, n = idx & 255;
        g_W1p[idx] = (k < KIN) ? f2tff(W1[k*HID + n]) : 0.f;
    } else if (idx < T1 + T2) {
        int j = idx - T1;
        int k = j / NOUT_PAD, n = j - k*NOUT_PAD;
        g_W2p[j] = (n < NOUT) ? f2tff(W2[k*NOUT + n]) : 0.f;
    }
}

__device__ __forceinline__ void mma_tf32(float c[4], unsigned a0, unsigned a1,
                                         unsigned a2, unsigned a3,
                                         unsigned b0, unsigned b1) {
    asm volatile(
        "mma.sync.aligned.m16n8k8.row.col.f32.tf32.tf32.f32 "
        "{%0,%1,%2,%3},{%4,%5,%6,%7},{%8,%9},{%0,%1,%2,%3};"
        : "+f"(c[0]), "+f"(c[1]), "+f"(c[2]), "+f"(c[3])
        : "r"(a0), "r"(a1), "r"(a2), "r"(a3), "r"(b0), "r"(b1));
}

__device__ __forceinline__ float softplus100(float z) {
    float y = 100.f * z;
    return 0.01f * (fmaxf(y, 0.f) + __logf(1.f + __expf(-fabsf(y))));
}

__device__ __forceinline__ void cp16(uint32_t dst, const float* src) {
    asm volatile("cp.async.cg.shared.global [%0], [%1], 16;" :: "r"(dst), "l"(src));
}
__device__ __forceinline__ void cp_commit() {
    asm volatile("cp.async.commit_group;");
}
__device__ __forceinline__ void cp_wait0() {
    asm volatile("cp.async.wait_group 0;" ::: "memory");
}

__global__ void __launch_bounds__(NTHREADS, 1)
tensosdf_main(const float* __restrict__ xyz,
              const float* __restrict__ b1, const float* __restrict__ b2,
              float* __restrict__ out) {
    extern __shared__ float smem[];
    float* sA  = smem;                 // hs[128][140] then h1s[128][260]
    float* ws  = smem + SM_WS_OFF;
    float* b1s = smem + SM_B1_OFF;
    float* b2s = smem + SM_B2_OFF;
    const uint32_t ws_s = (uint32_t)__cvta_generic_to_shared(ws);

    const int tid  = threadIdx.x;
    const int lane = tid & 31;
    const int warp = tid >> 5;
    const int pbase = blockIdx.x * TB;
    const int g = lane >> 2;
    const int t = lane & 3;

    // ---- biases ----
    if (tid < HID) b1s[tid] = b1[tid];
    else if (tid < HID + NOUT_PAD) {
        int c = tid - HID;
        b2s[c] = (c < NOUT) ? b2[c] : 0.f;
    }

    // ---- stage first W1 slab (async, overlaps gather) ----
    {
        const float* src0 = g_W1p;
        #pragma unroll
        for (int e = 0; e < 2; e++) {
            int idx = tid + e * NTHREADS;      // 0..2047
            int kk = idx >> 6, n4 = (idx & 63) << 2;
            cp16(ws_s + (uint32_t)(kk*WS_STRIDE + n4)*4u, src0 + kk*HID + n4);
        }
        cp_commit();
    }

    // ---- gather phase: warp handles 4 points ----
    {
        const unsigned FULL = 0xffffffffu;
        float vload = 0.f;
        int base3 = (pbase + warp*4)*3;
        if (lane < 12) vload = xyz[base3 + lane];

        const int i_of = (lane < 9) ? 0 : ((lane < 18) ? 1 : 2);
        const int cj = (lane - i_of*9) * 4;
        const bool act = lane < 27;

        #pragma unroll
        for (int pi = 0; pi < 4; pi++) {
            float x0 = __shfl_sync(FULL, vload, pi*3+0);
            float x1 = __shfl_sync(FULL, vload, pi*3+1);
            float x2 = __shfl_sync(FULL, vload, pi*3+2);
            float xn0 = 2.f*x0 - 1.f;
            float xn1 = 2.f*x1 - 1.f;
            float xn2 = 2.f*x2 - 1.f;
            float* hrow = sA + (warp*4 + pi) * HS_STRIDE;

            if (act) {
                // MAT_MODE = {(0,1),(0,2),(1,2)}; VEC_MODE = {2,1,0}
                float gx = (i_of == 2) ? xn1 : xn0;
                float gy = (i_of == 0) ? xn1 : xn2;
                float gl = (i_of == 0) ? xn2 : ((i_of == 1) ? xn1 : xn0);
                float px = (gx + 1.f) * 0.5f * 511.f;
                float py = (gy + 1.f) * 0.5f * 511.f;
                float pl = (gl + 1.f) * 0.5f * 511.f;
                int ix = min(max((int)floorf(px), 0), 510);
                int iy = min(max((int)floorf(py), 0), 510);
                int il = min(max((int)floorf(pl), 0), 510);
                float wx = px - (float)ix, wy = py - (float)iy, wl = pl - (float)il;
                const float* pb = g_planesT + (((i_of*GRIDSZ + iy)*GRIDSZ) + ix)*NC + cj;
                const float* lb = g_linesT + (i_of*GRIDSZ + il)*NC + cj;
                float4 f00 = *(const float4*)pb;
                float4 f01 = *(const float4*)(pb + NC);
                float4 f10 = *(const float4*)(pb + GRIDSZ*NC);
                float4 f11 = *(const float4*)(pb + GRIDSZ*NC + NC);
                float4 l0  = *(const float4*)lb;
                float4 l1  = *(const float4*)(lb + NC);
                float4 r;
                {
                    float fx0 = f00.x + wx*(f01.x - f00.x);
                    float fx1 = f10.x + wx*(f11.x - f10.x);
                    r.x = f2tff((fx0 + wy*(fx1 - fx0)) * (l0.x + wl*(l1.x - l0.x)));
                    fx0 = f00.y + wx*(f01.y - f00.y);
                    fx1 = f10.y + wx*(f11.y - f10.y);
                    r.y = f2tff((fx0 + wy*(fx1 - fx0)) * (l0.y + wl*(l1.y - l0.y)));
                    fx0 = f00.z + wx*(f01.z - f00.z);
                    fx1 = f10.z + wx*(f11.z - f10.z);
                    r.z = f2tff((fx0 + wy*(fx1 - fx0)) * (l0.z + wl*(l1.z - l0.z)));
                    fx0 = f00.w + wx*(f01.w - f00.w);
                    fx1 = f10.w + wx*(f11.w - f10.w);
                    r.w = f2tff((fx0 + wy*(fx1 - fx0)) * (l0.w + wl*(l1.w - l0.w)));
                }
                *(float4*)(hrow + i_of*NC + cj) = r;
            }

            // PE + zero-pad: lanes 0..31 -> hrow[108..139]
            float pv;
            if (lane < 3) {
                pv = (lane == 0) ? xn0 : ((lane == 1) ? xn1 : xn2);
            } else if (lane < 21) {
                int j = lane - 3;
                int f = j / 6;
                int rr = j - 6*f;
                int d = rr % 3;
                float xv = ((d == 0) ? xn0 : ((d == 1) ? xn1 : xn2)) * (float)(1 << f);
                pv = (rr < 3) ? __sinf(xv) : __cosf(xv);
            } else {
                pv = 0.f;
            }
            hrow[108 + lane] = f2tff(pv);
        }
    }

    cp_wait0();
    __syncthreads();

    // ================= GEMM1: 32 warps = 4m(32 rows) x 8n(32 cols) =================
    const int mt = warp & 3;
    const int nq = warp >> 2;          // 0..7
    const int arow = mt * 32;

    float acc[2][4][4];
    #pragma unroll
    for (int i = 0; i < 2; i++)
        #pragma unroll
        for (int j = 0; j < 4; j++)
            #pragma unroll
            for (int q = 0; q < 4; q++) acc[i][j][q] = 0.f;

    #pragma unroll
    for (int c = 0; c < 5; c++) {
        int buf = c & 1;
        if (c < 4) {   // prefetch next slab
            int rows = (c == 3) ? 8 : 32;
            const float* src0 = g_W1p + (c+1)*32*HID;
            uint32_t dbase = ws_s + (uint32_t)((buf^1)*WS_BUF)*4u;
            int nops = rows * 64;
            for (int idx = tid; idx < nops; idx += NTHREADS) {
                int kk = idx >> 6, n4 = (idx & 63) << 2;
                cp16(dbase + (uint32_t)(kk*WS_STRIDE + n4)*4u, src0 + kk*HID + n4);
            }
            cp_commit();
        }
        int nks = (c < 4) ? 4 : 1;
        #pragma unroll
        for (int kk8 = 0; kk8 < 4; kk8++) {
            if (kk8 >= nks) break;
            const float* Ab = sA + (arow + g)*HS_STRIDE + c*32 + kk8*8 + t;
            unsigned a00 = __float_as_uint(Ab[0]);
            unsigned a01 = __float_as_uint(Ab[8*HS_STRIDE]);
            unsigned a02 = __float_as_uint(Ab[4]);
            unsigned a03 = __float_as_uint(Ab[8*HS_STRIDE + 4]);
            const float* Ab2 = Ab + 16*HS_STRIDE;
            unsigned a10 = __float_as_uint(Ab2[0]);
            unsigned a11 = __float_as_uint(Ab2[8*HS_STRIDE]);
            unsigned a12 = __float_as_uint(Ab2[4]);
            unsigned a13 = __float_as_uint(Ab2[8*HS_STRIDE + 4]);
            const float* Bb = ws + buf*WS_BUF + (kk8*8 + t)*WS_STRIDE + nq*32 + g;
            #pragma unroll
            for (int nf = 0; nf < 4; nf++) {
                unsigned bb0 = __float_as_uint(Bb[nf*8]);
                unsigned bb1 = __float_as_uint(Bb[4*WS_STRIDE + nf*8]);
                mma_tf32(acc[0][nf], a00, a01, a02, a03, bb0, bb1);
                mma_tf32(acc[1][nf], a10, a11, a12, a13, bb0, bb1);
            }
        }
        if (c < 4) cp_wait0();
        __syncthreads();
    }

    // epilogue 1: bias + softplus -> h1s (tf32-rounded)
    #pragma unroll
    for (int mf = 0; mf < 2; mf++) {
        #pragma unroll
        for (int nf = 0; nf < 4; nf++) {
            int col = nq*32 + nf*8 + 2*t;
            float bb0 = b1s[col], bb1 = b1s[col+1];
            int row0 = arow + mf*16 + g;
            float r0 = f2tff(softplus100(acc[mf][nf][0] + bb0));
            float r1 = f2tff(softplus100(acc[mf][nf][1] + bb1));
            float r2 = f2tff(softplus100(acc[mf][nf][2] + bb0));
            float r3 = f2tff(softplus100(acc[mf][nf][3] + bb1));
            *(float2*)(sA + row0*H1_STRIDE + col)     = make_float2(r0, r1);
            *(float2*)(sA + (row0+8)*H1_STRIDE + col) = make_float2(r2, r3);
        }
    }

    // stage first W2 slab (32 rows x 160 cols)
    {
        const float* src0 = g_W2p;
        for (int idx = tid; idx < 32*40; idx += NTHREADS) {
            int kk = idx / 40, n4 = (idx - kk*40) << 2;
            cp16(ws_s + (uint32_t)(kk*WS2_STRIDE + n4)*4u, src0 + kk*NOUT_PAD + n4);
        }
        cp_commit();
    }
    cp_wait0();
    __syncthreads();

    // ================= GEMM2: 32 warps = 8m(16 rows) x 4n(40 cols) =================
    const int mt2 = warp & 7;
    const int nh2 = warp >> 3;         // 0..3
    const int arow2 = mt2 * 16;

    float acc2[5][4];
    #pragma unroll
    for (int i = 0; i < 5; i++)
        #pragma unroll
        for (int q = 0; q < 4; q++) acc2[i][q] = 0.f;

    #pragma unroll
    for (int c = 0; c < 8; c++) {
        int buf = c & 1;
        if (c < 7) {
            const float* src0 = g_W2p + (c+1)*32*NOUT_PAD;
            uint32_t dbase = ws_s + (uint32_t)((buf^1)*WS2_BUF)*4u;
            for (int idx = tid; idx < 32*40; idx += NTHREADS) {
                int kk = idx / 40, n4 = (idx - kk*40) << 2;
                cp16(dbase + (uint32_t)(kk*WS2_STRIDE + n4)*4u, src0 + kk*NOUT_PAD + n4);
            }
            cp_commit();
        }
        #pragma unroll
        for (int kk8 = 0; kk8 < 4; kk8++) {
            const float* Ab = sA + (arow2 + g)*H1_STRIDE + c*32 + kk8*8 + t;
            unsigned a0 = __float_as_uint(Ab[0]);
            unsigned a1 = __float_as_uint(Ab[8*H1_STRIDE]);
            unsigned a2 = __float_as_uint(Ab[4]);
            unsigned a3 = __float_as_uint(Ab[8*H1_STRIDE + 4]);
            const float* Bb = ws + buf*WS2_BUF + (kk8*8 + t)*WS2_STRIDE + nh2*40 + g;
            #pragma unroll
            for (int nf = 0; nf < 5; nf++) {
                unsigned bb0 = __float_as_uint(Bb[nf*8]);
                unsigned bb1 = __float_as_uint(Bb[4*WS2_STRIDE + nf*8]);
                mma_tf32(acc2[nf], a0, a1, a2, a3, bb0, bb1);
            }
        }
        if (c < 7) cp_wait0();
        __syncthreads();
    }

    // epilogue 2: bias + store
    #pragma unroll
    for (int nf = 0; nf < 5; nf++) {
        int col = nh2*40 + nf*8 + 2*t;
        float o0 = acc2[nf][0] + b2s[col];
        float o1 = acc2[nf][1] + b2s[col+1];
        float o2 = acc2[nf][2] + b2s[col];
        float o3 = acc2[nf][3] + b2s[col+1];
        int r0 = (pbase + arow2 + g) * NOUT;
        int r1 = (pbase + arow2 + g + 8) * NOUT;
        if (col < NOUT)     { out[r0 + col]     = o0; out[r1 + col]     = o2; }
        if (col + 1 < NOUT) { out[r0 + col + 1] = o1; out[r1 + col + 1] = o3; }
    }
}

extern "C" void kernel_launch(void* const* d_in, const int* in_sizes, int n_in,
                              void* d_out, int out_size) {
    const float* xyz    = (const float*)d_in[0];
    const float* planes = (const float*)d_in[1];
    const float* lines  = (const float*)d_in[2];
    const float* W1     = (const float*)d_in[3];
    const float* b1     = (const float*)d_in[4];
    const float* W2     = (const float*)d_in[5];
    const float* b2     = (const float*)d_in[6];
    float* out = (float*)d_out;

    static bool attr_set = false;
    if (!attr_set) {
        cudaFuncSetAttribute(tensosdf_main,
                             cudaFuncAttributeMaxDynamicSharedMemorySize, SMEM_BYTES);
        attr_set = true;
    }

    transpose_planes<<<3072, 256>>>(planes);
    transpose_lines<<<6, 256>>>(lines);
    const int npack = K1PAD*HID + HID*NOUT_PAD;
    pack_weights_kernel<<<(npack + 255) / 256, 256>>>(W1, W2);
    tensosdf_main<<<NPTS / TB, NTHREADS, SMEM_BYTES>>>(xyz, b1, b2, out);
}

// round 8
// speedup vs baseline: 1.5574x; 1.5574x over previous
#include <cuda_runtime.h>
#include <cuda_fp16.h>
#include <math.h>
#include <stdint.h>

#define NPTS      524288
#define GRIDSZ    512
#define NC        36
#define KIN       129
#define K1PAD     136
#define HID       256
#define NOUT      129
#define TB        128
#define NTHREADS  512

// ---- smem byte layout ----
// phase1: W1 [0,69632) ; A1 [69632,104448) ; A2 [104448,172032)
// phase2: W2 [0,84480)  (unioned with W1+A1 after GEMM1)
// biases: b1 f32 [172032,173056) ; b2 f32 [173056,173696)
#define BY_W1   0
#define BY_A1   69632
#define BY_A2   104448
#define BY_B1S  172032
#define BY_B2S  173056
#define SMEM_BYTES 173696

#define SA1_W 68          // A1 row stride in 32-bit words (136 halfs); 68%32=4 -> conflict-free
#define SW1_W 68          // W1 row stride (n-major)
#define SA2_W 132         // A2 row stride (264 halfs); 132%32=4 -> conflict-free
#define SW2_W 132         // W2 row stride

__device__ float g_planesT[3*GRIDSZ*GRIDSZ*NC];   // [i][y][x][c]
__device__ float g_linesT[3*GRIDSZ*NC];           // [i][l][c]
__device__ __align__(16) __half g_W1h[256*136];   // [n][k], fp16, zero-padded k>=129
__device__ __align__(16) __half g_W2h[160*264];   // [n][k], fp16, zero-padded n>=129 / k>=256

// ================= prep kernels =================
__global__ void __launch_bounds__(256) transpose_planes(const float* __restrict__ planes) {
    __shared__ float tile[8][32*37];
    int wid = threadIdx.x >> 5, lane = threadIdx.x & 31;
    int cell0 = (blockIdx.x * 8 + wid) * 32;
    int i = cell0 / (GRIDSZ*GRIDSZ);
    int rem = cell0 - i*GRIDSZ*GRIDSZ;
    int y = rem >> 9, x0 = rem & (GRIDSZ-1);
    const float* src = planes + (long)i*NC*GRIDSZ*GRIDSZ + (long)y*GRIDSZ + x0 + lane;
    float* t = tile[wid];
    #pragma unroll
    for (int c = 0; c < NC; c++) t[lane*37 + c] = src[(long)c*GRIDSZ*GRIDSZ];
    __syncwarp();
    float* dst = g_planesT + (long)cell0 * NC;
    #pragma unroll
    for (int k = 0; k < 9; k++) {
        int fo = (k*32 + lane) * 4;
        int cc = fo / NC, c = fo - cc*NC;
        *(float4*)(dst + fo) = make_float4(t[cc*37+c], t[cc*37+c+1], t[cc*37+c+2], t[cc*37+c+3]);
    }
}

__global__ void transpose_lines(const float* __restrict__ lines) {
    int t2 = blockIdx.x * blockDim.x + threadIdx.x;
    if (t2 < 3*GRIDSZ) {
        int j = t2 & (GRIDSZ-1), i = t2 >> 9;
        float* dst = g_linesT + t2*NC;
        const float* src = lines + (long)i*NC*GRIDSZ + j;
        #pragma unroll
        for (int c = 0; c < NC; c++) dst[c] = src[(long)c*GRIDSZ];
    }
}

__global__ void pack_weights_kernel(const float* __restrict__ W1, const float* __restrict__ W2) {
    int idx = blockIdx.x * blockDim.x + threadIdx.x;
    const int T1 = 256*136;          // 34816
    const int T2 = 160*264;          // 42240
    if (idx < T1) {
        int n = idx / 136, k = idx - n*136;
        g_W1h[idx] = (k < KIN) ? __float2half_rn(W1[k*HID + n]) : __float2half_rn(0.f);
    } else if (idx < T1 + T2) {
        int j = idx - T1;
        int n = j / 264, k = j - n*264;
        float v = (k < 256 && n < NOUT) ? W2[k*NOUT + n] : 0.f;
        g_W2h[j] = __float2half_rn(v);
    }
}

// ================= mma helpers =================
__device__ __forceinline__ void mma_f16_k16(float c[4], unsigned a0, unsigned a1,
                                            unsigned a2, unsigned a3,
                                            unsigned b0, unsigned b1) {
    asm volatile(
        "mma.sync.aligned.m16n8k16.row.col.f32.f16.f16.f32 "
        "{%0,%1,%2,%3},{%4,%5,%6,%7},{%8,%9},{%0,%1,%2,%3};"
        : "+f"(c[0]), "+f"(c[1]), "+f"(c[2]), "+f"(c[3])
        : "r"(a0), "r"(a1), "r"(a2), "r"(a3), "r"(b0), "r"(b1));
}
__device__ __forceinline__ void mma_f16_k8(float c[4], unsigned a0, unsigned a1, unsigned b0) {
    asm volatile(
        "mma.sync.aligned.m16n8k8.row.col.f32.f16.f16.f32 "
        "{%0,%1,%2,%3},{%4,%5},{%6},{%0,%1,%2,%3};"
        : "+f"(c[0]), "+f"(c[1]), "+f"(c[2]), "+f"(c[3])
        : "r"(a0), "r"(a1), "r"(b0));
}

__device__ __forceinline__ float softplus100(float z) {
    float y = 100.f * z;
    return 0.01f * (fmaxf(y, 0.f) + __logf(1.f + __expf(-fabsf(y))));
}
__device__ __forceinline__ void cp16(uint32_t dst, const void* src) {
    asm volatile("cp.async.cg.shared.global [%0], [%1], 16;" :: "r"(dst), "l"(src));
}
__device__ __forceinline__ void cp_commit() { asm volatile("cp.async.commit_group;"); }
__device__ __forceinline__ void cp_wait0()  { asm volatile("cp.async.wait_group 0;" ::: "memory"); }

// ================= main fused kernel =================
__global__ void __launch_bounds__(NTHREADS, 1)
tensosdf_main(const float* __restrict__ xyz,
              const float* __restrict__ b1, const float* __restrict__ b2,
              float* __restrict__ out) {
    extern __shared__ char smem[];
    const uint32_t smem_u32 = (uint32_t)__cvta_generic_to_shared(smem);
    float* b1s = (float*)(smem + BY_B1S);
    float* b2s = (float*)(smem + BY_B2S);

    const int tid  = threadIdx.x;
    const int lane = tid & 31;
    const int warp = tid >> 5;
    const int pbase = blockIdx.x * TB;
    const int g = lane >> 2;
    const int t = lane & 3;

    // ---- biases ----
    if (tid < HID) b1s[tid] = b1[tid];
    else if (tid < HID + 160) { int c = tid - HID; b2s[c] = (c < NOUT) ? b2[c] : 0.f; }

    // ---- stage W1 image (69632 B = 4352 x 16B), overlaps gather ----
    for (int idx = tid; idx < 4352; idx += NTHREADS)
        cp16(smem_u32 + BY_W1 + (uint32_t)idx*16u, (const char*)g_W1h + idx*16);
    cp_commit();

    // ---- gather: warp handles 8 points, writes fp16 A1 (stride 272B) ----
    {
        const unsigned FULL = 0xffffffffu;
        float vload = 0.f;
        int base3 = (pbase + warp*8)*3;
        if (lane < 24) vload = xyz[base3 + lane];

        const int i_of = (lane < 9) ? 0 : ((lane < 18) ? 1 : 2);
        const int cj = (lane - i_of*9) * 4;
        const bool act = lane < 27;
        const int fcol = i_of*NC + cj;
        const int pcol = 108 + lane;

        #pragma unroll
        for (int pi = 0; pi < 8; pi++) {
            float x0 = __shfl_sync(FULL, vload, pi*3+0);
            float x1 = __shfl_sync(FULL, vload, pi*3+1);
            float x2 = __shfl_sync(FULL, vload, pi*3+2);
            float xn0 = 2.f*x0 - 1.f, xn1 = 2.f*x1 - 1.f, xn2 = 2.f*x2 - 1.f;
            int row = warp*8 + pi;
            char* rbase = smem + BY_A1 + row*272;

            if (act) {
                float gx = (i_of == 2) ? xn1 : xn0;
                float gy = (i_of == 0) ? xn1 : xn2;
                float gl = (i_of == 0) ? xn2 : ((i_of == 1) ? xn1 : xn0);
                float px = (gx + 1.f) * 0.5f * 511.f;
                float py = (gy + 1.f) * 0.5f * 511.f;
                float pl = (gl + 1.f) * 0.5f * 511.f;
                int ix = min(max((int)floorf(px), 0), 510);
                int iy = min(max((int)floorf(py), 0), 510);
                int il = min(max((int)floorf(pl), 0), 510);
                float wx = px - ix, wy = py - iy, wl = pl - il;
                const float* pb = g_planesT + (((i_of*GRIDSZ + iy)*GRIDSZ) + ix)*NC + cj;
                const float* lb = g_linesT + (i_of*GRIDSZ + il)*NC + cj;
                float4 f00 = *(const float4*)pb;
                float4 f01 = *(const float4*)(pb + NC);
                float4 f10 = *(const float4*)(pb + GRIDSZ*NC);
                float4 f11 = *(const float4*)(pb + GRIDSZ*NC + NC);
                float4 l0  = *(const float4*)lb;
                float4 l1  = *(const float4*)(lb + NC);
                float rx, ry, rz, rw;
                float fx0 = f00.x + wx*(f01.x - f00.x), fx1 = f10.x + wx*(f11.x - f10.x);
                rx = (fx0 + wy*(fx1 - fx0)) * (l0.x + wl*(l1.x - l0.x));
                fx0 = f00.y + wx*(f01.y - f00.y); fx1 = f10.y + wx*(f11.y - f10.y);
                ry = (fx0 + wy*(fx1 - fx0)) * (l0.y + wl*(l1.y - l0.y));
                fx0 = f00.z + wx*(f01.z - f00.z); fx1 = f10.z + wx*(f11.z - f10.z);
                rz = (fx0 + wy*(fx1 - fx0)) * (l0.z + wl*(l1.z - l0.z));
                fx0 = f00.w + wx*(f01.w - f00.w); fx1 = f10.w + wx*(f11.w - f10.w);
                rw = (fx0 + wy*(fx1 - fx0)) * (l0.w + wl*(l1.w - l0.w));
                __half2 p0 = __float22half2_rn(make_float2(rx, ry));
                __half2 p1 = __float22half2_rn(make_float2(rz, rw));
                *(__half2*)(rbase + fcol*2)     = p0;
                *(__half2*)(rbase + fcol*2 + 4) = p1;
            }

            float pv;
            if (lane < 3) pv = (lane == 0) ? xn0 : ((lane == 1) ? xn1 : xn2);
            else if (lane < 21) {
                int j = lane - 3, f = j / 6, rr = j - 6*f, d = rr % 3;
                float xv = ((d == 0) ? xn0 : ((d == 1) ? xn1 : xn2)) * (float)(1 << f);
                pv = (rr < 3) ? __sinf(xv) : __cosf(xv);
            } else pv = 0.f;
            if (pcol < K1PAD)
                *(__half*)(rbase + pcol*2) = __float2half_rn(pv);
        }
    }

    cp_wait0();
    __syncthreads();

    // ================= GEMM1: 16 warps = 4m(32 rows) x 4n(64 cols) =================
    const int mt = warp & 3;
    const int nq = warp >> 2;          // 0..3
    const int arow = mt * 32;

    const uint32_t* Aw = (const uint32_t*)(smem + BY_A1);
    const uint32_t* Bw = (const uint32_t*)(smem + BY_W1);

    float acc[2][8][4];
    #pragma unroll
    for (int i = 0; i < 2; i++)
        #pragma unroll
        for (int j = 0; j < 8; j++)
            #pragma unroll
            for (int q = 0; q < 4; q++) acc[i][j][q] = 0.f;

    #pragma unroll
    for (int ks = 0; ks < 8; ks++) {
        const uint32_t* A0 = Aw + (arow + g)*SA1_W + ks*8 + t;
        unsigned a00 = A0[0], a02 = A0[4];
        unsigned a01 = A0[8*SA1_W], a03 = A0[8*SA1_W + 4];
        const uint32_t* A1p = A0 + 16*SA1_W;
        unsigned a10 = A1p[0], a12 = A1p[4];
        unsigned a11 = A1p[8*SA1_W], a13 = A1p[8*SA1_W + 4];
        const uint32_t* B0 = Bw + (nq*64 + g)*SW1_W + ks*8 + t;
        #pragma unroll
        for (int nf = 0; nf < 8; nf++) {
            unsigned bb0 = B0[nf*8*SW1_W];
            unsigned bb1 = B0[nf*8*SW1_W + 4];
            mma_f16_k16(acc[0][nf], a00, a01, a02, a03, bb0, bb1);
            mma_f16_k16(acc[1][nf], a10, a11, a12, a13, bb0, bb1);
        }
    }
    {   // k8 tail: k = 128..135
        const uint32_t* A0 = Aw + (arow + g)*SA1_W + 64 + t;
        unsigned a00 = A0[0], a01 = A0[8*SA1_W];
        unsigned a10 = A0[16*SA1_W], a11 = A0[24*SA1_W];
        const uint32_t* B0 = Bw + (nq*64 + g)*SW1_W + 64 + t;
        #pragma unroll
        for (int nf = 0; nf < 8; nf++) {
            unsigned bb0 = B0[nf*8*SW1_W];
            mma_f16_k8(acc[0][nf], a00, a01, bb0);
            mma_f16_k8(acc[1][nf], a10, a11, bb0);
        }
    }

    __syncthreads();   // all W1/A1 reads done

    // stage W2 image (84480 B = 5280 x 16B) into [0, 84480)
    for (int idx = tid; idx < 5280; idx += NTHREADS)
        cp16(smem_u32 + (uint32_t)idx*16u, (const char*)g_W2h + idx*16);
    cp_commit();

    // epilogue 1: bias + softplus -> fp16 A2 (stride 528B)
    #pragma unroll
    for (int mf = 0; mf < 2; mf++) {
        #pragma unroll
        for (int nf = 0; nf < 8; nf++) {
            int col = nq*64 + nf*8 + 2*t;
            float bb0 = b1s[col], bb1 = b1s[col+1];
            int row0 = arow + mf*16 + g;
            float r0 = softplus100(acc[mf][nf][0] + bb0);
            float r1 = softplus100(acc[mf][nf][1] + bb1);
            float r2 = softplus100(acc[mf][nf][2] + bb0);
            float r3 = softplus100(acc[mf][nf][3] + bb1);
            *(__half2*)(smem + BY_A2 + row0*528 + col*2)     = __float22half2_rn(make_float2(r0, r1));
            *(__half2*)(smem + BY_A2 + (row0+8)*528 + col*2) = __float22half2_rn(make_float2(r2, r3));
        }
    }

    cp_wait0();
    __syncthreads();

    // ================= GEMM2: 16 warps = 4m(32 rows) x 4n(40 cols) =================
    const uint32_t* Aw2 = (const uint32_t*)(smem + BY_A2);
    const uint32_t* Bw2 = (const uint32_t*)(smem + 0);
    const int ng2 = warp >> 2;        // 0..3, 40 cols each

    float acc2[2][5][4];
    #pragma unroll
    for (int i = 0; i < 2; i++)
        #pragma unroll
        for (int j = 0; j < 5; j++)
            #pragma unroll
            for (int q = 0; q < 4; q++) acc2[i][j][q] = 0.f;

    #pragma unroll
    for (int ks = 0; ks < 16; ks++) {
        const uint32_t* A0 = Aw2 + (arow + g)*SA2_W + ks*8 + t;
        unsigned a00 = A0[0], a02 = A0[4];
        unsigned a01 = A0[8*SA2_W], a03 = A0[8*SA2_W + 4];
        const uint32_t* A1p = A0 + 16*SA2_W;
        unsigned a10 = A1p[0], a12 = A1p[4];
        unsigned a11 = A1p[8*SA2_W], a13 = A1p[8*SA2_W + 4];
        const uint32_t* B0 = Bw2 + (ng2*40 + g)*SW2_W + ks*8 + t;
        #pragma unroll
        for (int nf = 0; nf < 5; nf++) {
            unsigned bb0 = B0[nf*8*SW2_W];
            unsigned bb1 = B0[nf*8*SW2_W + 4];
            mma_f16_k16(acc2[0][nf], a00, a01, a02, a03, bb0, bb1);
            mma_f16_k16(acc2[1][nf], a10, a11, a12, a13, bb0, bb1);
        }
    }

    // epilogue 2: bias + store
    #pragma unroll
    for (int mf = 0; mf < 2; mf++) {
        #pragma unroll
        for (int nf = 0; nf < 5; nf++) {
            int col = ng2*40 + nf*8 + 2*t;
            float o0 = acc2[mf][nf][0] + b2s[col];
            float o1 = acc2[mf][nf][1] + b2s[col+1];
            float o2 = acc2[mf][nf][2] + b2s[col];
            float o3 = acc2[mf][nf][3] + b2s[col+1];
            int r0 = (pbase + arow + mf*16 + g) * NOUT;
            int r1 = r0 + 8*NOUT;
            if (col < NOUT)     { out[r0 + col]     = o0; out[r1 + col]     = o2; }
            if (col + 1 < NOUT) { out[r0 + col + 1] = o1; out[r1 + col + 1] = o3; }
        }
    }
}

extern "C" void kernel_launch(void* const* d_in, const int* in_sizes, int n_in,
                              void* d_out, int out_size) {
    const float* xyz    = (const float*)d_in[0];
    const float* planes = (const float*)d_in[1];
    const float* lines  = (const float*)d_in[2];
    const float* W1     = (const float*)d_in[3];
    const float* b1     = (const float*)d_in[4];
    const float* W2     = (const float*)d_in[5];
    const float* b2     = (const float*)d_in[6];
    float* out = (float*)d_out;

    static bool attr_set = false;
    if (!attr_set) {
        cudaFuncSetAttribute(tensosdf_main,
                             cudaFuncAttributeMaxDynamicSharedMemorySize, SMEM_BYTES);
        attr_set = true;
    }

    transpose_planes<<<3072, 256>>>(planes);
    transpose_lines<<<6, 256>>>(lines);
    const int npack = 256*136 + 160*264;
    pack_weights_kernel<<<(npack + 255) / 256, 256>>>(W1, W2);
    tensosdf_main<<<NPTS / TB, NTHREADS, SMEM_BYTES>>>(xyz, b1, b2, out);
}